// round 15
// baseline (speedup 1.0000x reference)
#include <cuda_runtime.h>
#include <cuda_fp16.h>
#include <cstdint>

#define N_ROWS 8192
#define FFN    4096
#define EMB    1024

// ---------------- HMMA GEMM config (R12 exact, known-good 172.4us) ----------------
#define BM 128
#define BN 128
#define BK 64
#define STAGES 3
#define KITERS (FFN / BK)                       // 64
#define A_STAGE_BYTES (BM * BK * 2)             // 16 KB
#define B_STAGE_BYTES (BN * BK * 2)             // 16 KB
#define STAGE_BYTES (A_STAGE_BYTES + B_STAGE_BYTES)   // 32 KB
#define SMEM_TOTAL (STAGES * STAGE_BYTES)       // 96 KB -> 2 CTAs/SM

#define GELU_BLOCKS  4096                       // 33.5M / (256*32)
#define WCONV_BLOCKS 2048                       // 4.19M / (256*8)
#define PREP_BLOCKS (GELU_BLOCKS + WCONV_BLOCKS + 1)

// Static scratch (allocation-free rule)
__device__ __align__(16) __half g_h[(size_t)N_ROWS * FFN];   // gelu(x)*mask*scale
__device__ __align__(16) __half g_w[(size_t)EMB * FFN];      // weight fp16
__device__ __align__(16) __half g_bias[EMB];

// ---------------------------------------------------------------------------
// Warp-local sniff: classify buffer order + dtype scenario from 32 words each.
// ---------------------------------------------------------------------------
__device__ __forceinline__ void sniff(const unsigned* A, const unsigned* B,
                                      int& sw, int& f32) {
    int lane = threadIdx.x & 31;
    unsigned a = __ldg(A + lane);
    unsigned b = __ldg(B + lane);
    unsigned wa = __ballot_sync(~0u, a <= 1u);
    unsigned wb = __ballot_sync(~0u, b <= 1u);
    unsigned ba = __ballot_sync(~0u, (a & 0xFEFEFEFEu) == 0u);
    unsigned bb = __ballot_sync(~0u, (b & 0xFEFEFEFEu) == 0u);
    if      (wb == ~0u) { sw = 0; f32 = 1; }
    else if (wa == ~0u) { sw = 1; f32 = 1; }
    else if (bb == ~0u) { sw = 0; f32 = 0; }
    else if (ba == ~0u) { sw = 1; f32 = 0; }
    else                { sw = 0; f32 = 1; }
}

// GELU, tanh-form with HW tanh.approx.f32 (passes at rel_err 2.97e-4)
__device__ __forceinline__ __half gelu_h(float x) {
    float u = 0.7978845608028654f * fmaf(0.044715f * x, x * x, x);
    float t;
    asm("tanh.approx.f32 %0, %1;" : "=f"(t) : "f"(u));
    return __float2half(0.5f * x * (1.0f + t));
}

// ---------------------------------------------------------------------------
// Prep (single launch): gelu+mask -> g_h (32 elems/thread, 2 halves of 16);
// weight -> g_w ; bias -> g_bias
// ---------------------------------------------------------------------------
__global__ void __launch_bounds__(256) prep_k(const void* __restrict__ A,
                                              const void* __restrict__ B,
                                              const void* __restrict__ w,
                                              const void* __restrict__ bias) {
    int sw, f32;
    sniff((const unsigned*)A, (const unsigned*)B, sw, f32);

    const __half sc = __float2half(1.0f / 0.9f);
    const __half hz = __ushort_as_half((unsigned short)0);

    unsigned bidx = blockIdx.x;
    if (bidx < GELU_BLOCKS) {
        const char* xp = (const char*)(sw ? B : A);
        const char* mp = (const char*)(sw ? A : B);
        size_t base = ((size_t)bidx * 256 + threadIdx.x) * 32;

#pragma unroll
        for (int h = 0; h < 2; h++) {            // two 16-elem halves
            size_t idx = base + h * 16;
            __half hs[16];
            if (f32) {
                const float4* xv4 = (const float4*)(xp + idx * 4);
                const int4*   mv4 = (const int4*)(mp + idx * 4);
                float4 xv[4]; int4 mv[4];
#pragma unroll
                for (int i = 0; i < 4; i++) xv[i] = xv4[i];   // 4 x LDG.128
#pragma unroll
                for (int i = 0; i < 4; i++) mv[i] = mv4[i];   // 4 x LDG.128
#pragma unroll
                for (int i = 0; i < 4; i++) {
                    hs[i*4+0] = mv[i].x ? __hmul(gelu_h(xv[i].x), sc) : hz;
                    hs[i*4+1] = mv[i].y ? __hmul(gelu_h(xv[i].y), sc) : hz;
                    hs[i*4+2] = mv[i].z ? __hmul(gelu_h(xv[i].z), sc) : hz;
                    hs[i*4+3] = mv[i].w ? __hmul(gelu_h(xv[i].w), sc) : hz;
                }
            } else {
                uint4 hv0 = ((const uint4*)(xp + idx * 2))[0];
                uint4 hv1 = ((const uint4*)(xp + idx * 2))[1];
                uint4 mb  = *(const uint4*)(mp + idx);
                __half xs[16];
                *reinterpret_cast<uint4*>(xs)     = hv0;
                *reinterpret_cast<uint4*>(xs + 8) = hv1;
                unsigned mw[4] = {mb.x, mb.y, mb.z, mb.w};
#pragma unroll
                for (int i = 0; i < 16; i++) {
                    unsigned keep = (mw[i >> 2] >> ((i & 3) * 8)) & 0xFFu;
                    hs[i] = keep ? __hmul(gelu_h(__half2float(xs[i])), sc) : hz;
                }
            }
            ((uint4*)(g_h + idx))[0] = reinterpret_cast<uint4*>(hs)[0];
            ((uint4*)(g_h + idx))[1] = reinterpret_cast<uint4*>(hs)[1];
        }
    } else if (bidx < GELU_BLOCKS + WCONV_BLOCKS) {
        size_t i = ((size_t)(bidx - GELU_BLOCKS) * 256 + threadIdx.x) * 8;
        if (f32) {
            const float4* wv4 = (const float4*)((const float*)w + i);
            float4 v0 = wv4[0], v1 = wv4[1];
            __half h[8] = {__float2half(v0.x), __float2half(v0.y),
                           __float2half(v0.z), __float2half(v0.w),
                           __float2half(v1.x), __float2half(v1.y),
                           __float2half(v1.z), __float2half(v1.w)};
            *reinterpret_cast<uint4*>(g_w + i) = *reinterpret_cast<uint4*>(h);
        } else {
            *reinterpret_cast<uint4*>(g_w + i) = *(const uint4*)((const __half*)w + i);
        }
    } else {
        int i = threadIdx.x * 4;
        if (i < EMB) {
            if (f32) {
                float4 v = *(const float4*)((const float*)bias + i);
                __half h[4] = {__float2half(v.x), __float2half(v.y),
                               __float2half(v.z), __float2half(v.w)};
                *reinterpret_cast<uint2*>(g_bias + i) = *reinterpret_cast<uint2*>(h);
            } else {
                *reinterpret_cast<uint2*>(g_bias + i) = *(const uint2*)((const __half*)bias + i);
            }
        }
    }
}

// ---------------------------------------------------------------------------
// Pass 2: y = g_h @ g_w^T + bias  (M=8192, N=1024, K=4096)
// R12 exact: 256 threads = 8 warps (2x4), warp tile 64x32, 3-stage cp.async
// (fill AFTER compute), SW128, BK=64, 2 CTAs/SM.
// ---------------------------------------------------------------------------
__global__ void __launch_bounds__(256, 2) gemm_k(void* __restrict__ outv,
                                                 const void* __restrict__ A0,
                                                 const void* __restrict__ B0) {
    extern __shared__ __align__(1024) char sm[];
    const uint32_t smem_base = (uint32_t)__cvta_generic_to_shared(sm);

    int snsw, f32o;
    sniff((const unsigned*)A0, (const unsigned*)B0, snsw, f32o);

    const int tid  = threadIdx.x;
    const int lane = tid & 31;
    const int warp = tid >> 5;
    const int wm   = (warp >> 2) * 64;
    const int wn   = (warp & 3) * 32;

    const int mBase = blockIdx.y * BM;
    const int nBase = blockIdx.x * BN;

    const __half* Aglob = g_h + (size_t)mBase * FFN;
    const __half* Bglob = g_w + (size_t)nBase * FFN;

    float acc[4][4][4];
#pragma unroll
    for (int a = 0; a < 4; a++)
#pragma unroll
        for (int b = 0; b < 4; b++)
#pragma unroll
            for (int c = 0; c < 4; c++) acc[a][b][c] = 0.f;

    auto swz = [](uint32_t off) -> uint32_t { return off ^ ((off >> 3) & 0x70); };

    auto fill = [&](int kt) {
        int buf = kt % STAGES;
        uint32_t sA = smem_base + buf * STAGE_BYTES;
        uint32_t sB = sA + A_STAGE_BYTES;
        const __half* Ag = Aglob + kt * BK;
        const __half* Bg = Bglob + kt * BK;
#pragma unroll
        for (int i = 0; i < 4; i++) {
            int idx = tid + (i << 8);
            int row = idx >> 3, c = idx & 7;
            uint32_t off = (uint32_t)(row * 128 + c * 16);
            asm volatile("cp.async.cg.shared.global [%0], [%1], 16;"
                         :: "r"(sA + (off ^ ((off >> 3) & 0x70))),
                            "l"(Ag + (size_t)row * FFN + c * 8));
        }
#pragma unroll
        for (int i = 0; i < 4; i++) {
            int idx = tid + (i << 8);
            int row = idx >> 3, c = idx & 7;
            uint32_t off = (uint32_t)(row * 128 + c * 16);
            asm volatile("cp.async.cg.shared.global [%0], [%1], 16;"
                         :: "r"(sB + (off ^ ((off >> 3) & 0x70))),
                            "l"(Bg + (size_t)row * FFN + c * 8));
        }
        asm volatile("cp.async.commit_group;");
    };

    fill(0); fill(1);

    for (int kt = 0; kt < KITERS; ++kt) {
        if (kt + 1 < KITERS) asm volatile("cp.async.wait_group 1;");
        else                 asm volatile("cp.async.wait_group 0;");
        __syncthreads();

        int buf = kt % STAGES;
        uint32_t sA = smem_base + buf * STAGE_BYTES;
        uint32_t sB = sA + A_STAGE_BYTES;

#pragma unroll
        for (int ks = 0; ks < 4; ks++) {
            uint32_t a[4][4];
#pragma unroll
            for (int mi = 0; mi < 4; mi++) {
                int r = wm + mi * 16 + ((lane >> 3) & 1) * 8 + (lane & 7);
                int c = ks * 16 + (lane >> 4) * 8;
                uint32_t addr = sA + swz((uint32_t)(r * 128 + c * 2));
                asm volatile("ldmatrix.sync.aligned.m8n8.x4.shared.b16 {%0,%1,%2,%3}, [%4];"
                             : "=r"(a[mi][0]), "=r"(a[mi][1]), "=r"(a[mi][2]), "=r"(a[mi][3])
                             : "r"(addr));
            }
            uint32_t b[4][2];
#pragma unroll
            for (int nj = 0; nj < 2; nj++) {
                int r = wn + nj * 16 + (lane >> 4) * 8 + (lane & 7);
                int c = ks * 16 + ((lane >> 3) & 1) * 8;
                uint32_t addr = sB + swz((uint32_t)(r * 128 + c * 2));
                asm volatile("ldmatrix.sync.aligned.m8n8.x4.shared.b16 {%0,%1,%2,%3}, [%4];"
                             : "=r"(b[2 * nj][0]), "=r"(b[2 * nj][1]),
                               "=r"(b[2 * nj + 1][0]), "=r"(b[2 * nj + 1][1])
                             : "r"(addr));
            }
#pragma unroll
            for (int mi = 0; mi < 4; mi++)
#pragma unroll
                for (int ni = 0; ni < 4; ni++) {
                    asm volatile(
                        "mma.sync.aligned.m16n8k16.row.col.f32.f16.f16.f32 "
                        "{%0,%1,%2,%3}, {%4,%5,%6,%7}, {%8,%9}, {%0,%1,%2,%3};"
                        : "+f"(acc[mi][ni][0]), "+f"(acc[mi][ni][1]),
                          "+f"(acc[mi][ni][2]), "+f"(acc[mi][ni][3])
                        : "r"(a[mi][0]), "r"(a[mi][1]), "r"(a[mi][2]), "r"(a[mi][3]),
                          "r"(b[ni][0]), "r"(b[ni][1]));
                }
        }
        if (kt + STAGES - 1 < KITERS) fill(kt + STAGES - 1);
    }

    // Epilogue: fp16(acc) + fp16 bias, store per __output__ dtype
#pragma unroll
    for (int mi = 0; mi < 4; mi++) {
#pragma unroll
        for (int ni = 0; ni < 4; ni++) {
            int row = mBase + wm + mi * 16 + (lane >> 2);
            int col = nBase + wn + ni * 8 + (lane & 3) * 2;
            __half2 b2 = *reinterpret_cast<const __half2*>(g_bias + col);
            __half2 v0 = __halves2half2(__float2half(acc[mi][ni][0]),
                                        __float2half(acc[mi][ni][1]));
            v0 = __hadd2(v0, b2);
            __half2 v1 = __halves2half2(__float2half(acc[mi][ni][2]),
                                        __float2half(acc[mi][ni][3]));
            v1 = __hadd2(v1, b2);
            if (f32o) {
                float* out = (float*)outv;
                *reinterpret_cast<float2*>(out + (size_t)row * EMB + col) =
                    make_float2(__low2float(v0), __high2float(v0));
                *reinterpret_cast<float2*>(out + (size_t)(row + 8) * EMB + col) =
                    make_float2(__low2float(v1), __high2float(v1));
            } else {
                __half* out = (__half*)outv;
                *reinterpret_cast<__half2*>(out + (size_t)row * EMB + col) = v0;
                *reinterpret_cast<__half2*>(out + (size_t)(row + 8) * EMB + col) = v1;
            }
        }
    }
}

// ---------------------------------------------------------------------------
extern "C" void kernel_launch(void* const* d_in, const int* in_sizes, int n_in,
                              void* d_out, int out_size) {
    const void* bigA = nullptr;
    const void* bigB = nullptr;
    const void* w    = nullptr;
    const void* bias = nullptr;
    for (int i = 0; i < n_in; i++) {
        if (in_sizes[i] == EMB)            bias = d_in[i];
        else if (in_sizes[i] == EMB * FFN) w    = d_in[i];
        else if (!bigA)                    bigA = d_in[i];
        else                               bigB = d_in[i];
    }

    prep_k<<<PREP_BLOCKS, 256>>>(bigA, bigB, w, bias);

    static int smem_set = 0;
    if (!smem_set) {
        cudaFuncSetAttribute(gemm_k, cudaFuncAttributeMaxDynamicSharedMemorySize, SMEM_TOTAL);
        smem_set = 1;
    }
    dim3 grid(EMB / BN, N_ROWS / BM);   // 8 x 64 = 512 CTAs, n-tiles fast
    gemm_k<<<grid, 256, SMEM_TOTAL>>>(d_out, bigA, bigB);
}

// round 17
// speedup vs baseline: 1.0576x; 1.0576x over previous
#include <cuda_runtime.h>
#include <cuda_fp16.h>
#include <cstdint>

#define N_ROWS 8192
#define FFN    4096
#define EMB    1024

// ---------------- HMMA GEMM config (R12 exact core, 172.4us) ----------------
#define BM 128
#define BN 128
#define BK 64
#define STAGES 3
#define KITERS (FFN / BK)                       // 64
#define A_STAGE_BYTES (BM * BK * 2)             // 16 KB
#define B_STAGE_BYTES (BN * BK * 2)             // 16 KB
#define STAGE_BYTES (A_STAGE_BYTES + B_STAGE_BYTES)   // 32 KB
#define SMEM_TOTAL (STAGES * STAGE_BYTES)       // 96 KB -> 2 CTAs/SM

#define GELU_BLOCKS  8192                       // 33.5M / (256*16)  (R12 prep)
#define WCONV_BLOCKS 2048                       // 4.19M / (256*8)
#define PREP_BLOCKS (GELU_BLOCKS + WCONV_BLOCKS + 1)

// Epilogue staging row pitches (words), padded for alignment + bank rotation
#define EPI_F32_PITCH 132
#define EPI_F16_PITCH 68

// Static scratch (allocation-free rule)
__device__ __align__(16) __half g_h[(size_t)N_ROWS * FFN];   // gelu(x)*mask*scale
__device__ __align__(16) __half g_w[(size_t)EMB * FFN];      // weight fp16
__device__ __align__(16) __half g_bias[EMB];

__device__ __forceinline__ uint32_t h2_bits(__half2 v) {
    return *reinterpret_cast<uint32_t*>(&v);
}

// ---------------------------------------------------------------------------
// Warp-local sniff: classify buffer order + dtype scenario from 32 words each.
// ---------------------------------------------------------------------------
__device__ __forceinline__ void sniff(const unsigned* A, const unsigned* B,
                                      int& sw, int& f32) {
    int lane = threadIdx.x & 31;
    unsigned a = __ldg(A + lane);
    unsigned b = __ldg(B + lane);
    unsigned wa = __ballot_sync(~0u, a <= 1u);
    unsigned wb = __ballot_sync(~0u, b <= 1u);
    unsigned ba = __ballot_sync(~0u, (a & 0xFEFEFEFEu) == 0u);
    unsigned bb = __ballot_sync(~0u, (b & 0xFEFEFEFEu) == 0u);
    if      (wb == ~0u) { sw = 0; f32 = 1; }
    else if (wa == ~0u) { sw = 1; f32 = 1; }
    else if (bb == ~0u) { sw = 0; f32 = 0; }
    else if (ba == ~0u) { sw = 1; f32 = 0; }
    else                { sw = 0; f32 = 1; }
}

// GELU, tanh-form with HW tanh.approx.f32 (passes at rel_err 2.97e-4)
__device__ __forceinline__ __half gelu_h(float x) {
    float u = 0.7978845608028654f * fmaf(0.044715f * x, x * x, x);
    float t;
    asm("tanh.approx.f32 %0, %1;" : "=f"(t) : "f"(u));
    return __float2half(0.5f * x * (1.0f + t));
}

// ---------------------------------------------------------------------------
// Prep (single launch, R12-exact 16 elem/thread): gelu+mask -> g_h ; W ; bias
// ---------------------------------------------------------------------------
__global__ void __launch_bounds__(256) prep_k(const void* __restrict__ A,
                                              const void* __restrict__ B,
                                              const void* __restrict__ w,
                                              const void* __restrict__ bias) {
    int sw, f32;
    sniff((const unsigned*)A, (const unsigned*)B, sw, f32);

    const __half sc = __float2half(1.0f / 0.9f);
    const __half hz = __ushort_as_half((unsigned short)0);

    unsigned bidx = blockIdx.x;
    if (bidx < GELU_BLOCKS) {
        const char* xp = (const char*)(sw ? B : A);
        const char* mp = (const char*)(sw ? A : B);
        size_t idx = ((size_t)bidx * 256 + threadIdx.x) * 16;

        __half hs[16];
        if (f32) {
            const float4* xv4 = (const float4*)(xp + idx * 4);
            const int4*   mv4 = (const int4*)(mp + idx * 4);
            float4 xv[4]; int4 mv[4];
#pragma unroll
            for (int i = 0; i < 4; i++) xv[i] = xv4[i];   // 4 x LDG.128
#pragma unroll
            for (int i = 0; i < 4; i++) mv[i] = mv4[i];   // 4 x LDG.128
#pragma unroll
            for (int i = 0; i < 4; i++) {
                hs[i*4+0] = mv[i].x ? __hmul(gelu_h(xv[i].x), sc) : hz;
                hs[i*4+1] = mv[i].y ? __hmul(gelu_h(xv[i].y), sc) : hz;
                hs[i*4+2] = mv[i].z ? __hmul(gelu_h(xv[i].z), sc) : hz;
                hs[i*4+3] = mv[i].w ? __hmul(gelu_h(xv[i].w), sc) : hz;
            }
        } else {
            uint4 hv0 = ((const uint4*)(xp + idx * 2))[0];
            uint4 hv1 = ((const uint4*)(xp + idx * 2))[1];
            uint4 mb  = *(const uint4*)(mp + idx);
            __half xs[16];
            *reinterpret_cast<uint4*>(xs)     = hv0;
            *reinterpret_cast<uint4*>(xs + 8) = hv1;
            unsigned mw[4] = {mb.x, mb.y, mb.z, mb.w};
#pragma unroll
            for (int i = 0; i < 16; i++) {
                unsigned keep = (mw[i >> 2] >> ((i & 3) * 8)) & 0xFFu;
                hs[i] = keep ? __hmul(gelu_h(__half2float(xs[i])), sc) : hz;
            }
        }
        ((uint4*)(g_h + idx))[0] = reinterpret_cast<uint4*>(hs)[0];
        ((uint4*)(g_h + idx))[1] = reinterpret_cast<uint4*>(hs)[1];
    } else if (bidx < GELU_BLOCKS + WCONV_BLOCKS) {
        size_t i = ((size_t)(bidx - GELU_BLOCKS) * 256 + threadIdx.x) * 8;
        if (f32) {
            const float4* wv4 = (const float4*)((const float*)w + i);
            float4 v0 = wv4[0], v1 = wv4[1];
            __half h[8] = {__float2half(v0.x), __float2half(v0.y),
                           __float2half(v0.z), __float2half(v0.w),
                           __float2half(v1.x), __float2half(v1.y),
                           __float2half(v1.z), __float2half(v1.w)};
            *reinterpret_cast<uint4*>(g_w + i) = *reinterpret_cast<uint4*>(h);
        } else {
            *reinterpret_cast<uint4*>(g_w + i) = *(const uint4*)((const __half*)w + i);
        }
    } else {
        int i = threadIdx.x * 4;
        if (i < EMB) {
            if (f32) {
                float4 v = *(const float4*)((const float*)bias + i);
                __half h[4] = {__float2half(v.x), __float2half(v.y),
                               __float2half(v.z), __float2half(v.w)};
                *reinterpret_cast<uint2*>(g_bias + i) = *reinterpret_cast<uint2*>(h);
            } else {
                *reinterpret_cast<uint2*>(g_bias + i) = *(const uint2*)((const __half*)bias + i);
            }
        }
    }
}

// ---------------------------------------------------------------------------
// Pass 2: y = g_h @ g_w^T + bias  (M=8192, N=1024, K=4096)
// R12 core (fill AFTER compute, SW128, BK=64, 2 CTAs/SM) + smem-staged
// coalesced epilogue + reversed-m grid (wave1 uses freshest L2 h rows).
// ---------------------------------------------------------------------------
__global__ void __launch_bounds__(256, 2) gemm_k(void* __restrict__ outv,
                                                 const void* __restrict__ A0,
                                                 const void* __restrict__ B0) {
    extern __shared__ __align__(1024) char sm[];
    const uint32_t smem_base = (uint32_t)__cvta_generic_to_shared(sm);

    int snsw, f32o;
    sniff((const unsigned*)A0, (const unsigned*)B0, snsw, f32o);

    const int tid  = threadIdx.x;
    const int lane = tid & 31;
    const int warp = tid >> 5;
    const int wm   = (warp >> 2) * 64;
    const int wn   = (warp & 3) * 32;

    const int mBase = (gridDim.y - 1 - blockIdx.y) * BM;   // reversed m
    const int nBase = blockIdx.x * BN;

    const __half* Aglob = g_h + (size_t)mBase * FFN;
    const __half* Bglob = g_w + (size_t)nBase * FFN;

    float acc[4][4][4];
#pragma unroll
    for (int a = 0; a < 4; a++)
#pragma unroll
        for (int b = 0; b < 4; b++)
#pragma unroll
            for (int c = 0; c < 4; c++) acc[a][b][c] = 0.f;

    auto swz = [](uint32_t off) -> uint32_t { return off ^ ((off >> 3) & 0x70); };

    auto fill = [&](int kt) {
        int buf = kt % STAGES;
        uint32_t sA = smem_base + buf * STAGE_BYTES;
        uint32_t sB = sA + A_STAGE_BYTES;
        const __half* Ag = Aglob + kt * BK;
        const __half* Bg = Bglob + kt * BK;
#pragma unroll
        for (int i = 0; i < 4; i++) {
            int idx = tid + (i << 8);
            int row = idx >> 3, c = idx & 7;
            uint32_t off = (uint32_t)(row * 128 + c * 16);
            asm volatile("cp.async.cg.shared.global [%0], [%1], 16;"
                         :: "r"(sA + (off ^ ((off >> 3) & 0x70))),
                            "l"(Ag + (size_t)row * FFN + c * 8));
        }
#pragma unroll
        for (int i = 0; i < 4; i++) {
            int idx = tid + (i << 8);
            int row = idx >> 3, c = idx & 7;
            uint32_t off = (uint32_t)(row * 128 + c * 16);
            asm volatile("cp.async.cg.shared.global [%0], [%1], 16;"
                         :: "r"(sB + (off ^ ((off >> 3) & 0x70))),
                            "l"(Bg + (size_t)row * FFN + c * 8));
        }
        asm volatile("cp.async.commit_group;");
    };

    fill(0); fill(1);

    for (int kt = 0; kt < KITERS; ++kt) {
        if (kt + 1 < KITERS) asm volatile("cp.async.wait_group 1;");
        else                 asm volatile("cp.async.wait_group 0;");
        __syncthreads();

        int buf = kt % STAGES;
        uint32_t sA = smem_base + buf * STAGE_BYTES;
        uint32_t sB = sA + A_STAGE_BYTES;

#pragma unroll
        for (int ks = 0; ks < 4; ks++) {
            uint32_t a[4][4];
#pragma unroll
            for (int mi = 0; mi < 4; mi++) {
                int r = wm + mi * 16 + ((lane >> 3) & 1) * 8 + (lane & 7);
                int c = ks * 16 + (lane >> 4) * 8;
                uint32_t addr = sA + swz((uint32_t)(r * 128 + c * 2));
                asm volatile("ldmatrix.sync.aligned.m8n8.x4.shared.b16 {%0,%1,%2,%3}, [%4];"
                             : "=r"(a[mi][0]), "=r"(a[mi][1]), "=r"(a[mi][2]), "=r"(a[mi][3])
                             : "r"(addr));
            }
            uint32_t b[4][2];
#pragma unroll
            for (int nj = 0; nj < 2; nj++) {
                int r = wn + nj * 16 + (lane >> 4) * 8 + (lane & 7);
                int c = ks * 16 + ((lane >> 3) & 1) * 8;
                uint32_t addr = sB + swz((uint32_t)(r * 128 + c * 2));
                asm volatile("ldmatrix.sync.aligned.m8n8.x4.shared.b16 {%0,%1,%2,%3}, [%4];"
                             : "=r"(b[2 * nj][0]), "=r"(b[2 * nj][1]),
                               "=r"(b[2 * nj + 1][0]), "=r"(b[2 * nj + 1][1])
                             : "r"(addr));
            }
#pragma unroll
            for (int mi = 0; mi < 4; mi++)
#pragma unroll
                for (int ni = 0; ni < 4; ni++) {
                    asm volatile(
                        "mma.sync.aligned.m16n8k16.row.col.f32.f16.f16.f32 "
                        "{%0,%1,%2,%3}, {%4,%5,%6,%7}, {%8,%9}, {%0,%1,%2,%3};"
                        : "+f"(acc[mi][ni][0]), "+f"(acc[mi][ni][1]),
                          "+f"(acc[mi][ni][2]), "+f"(acc[mi][ni][3])
                        : "r"(a[mi][0]), "r"(a[mi][1]), "r"(a[mi][2]), "r"(a[mi][3]),
                          "r"(b[ni][0]), "r"(b[ni][1]));
                }
        }
        if (kt + STAGES - 1 < KITERS) fill(kt + STAGES - 1);
    }

    // ---- Epilogue: fp16(acc)+bias -> smem stage -> fully coalesced STG.128 ----
    __syncthreads();   // all warps done with pipeline smem

    if (f32o) {
        float* smf = reinterpret_cast<float*>(sm);
#pragma unroll
        for (int mi = 0; mi < 4; mi++) {
#pragma unroll
            for (int ni = 0; ni < 4; ni++) {
                int row  = wm + mi * 16 + (lane >> 2);
                int colw = wn + ni * 8 + (lane & 3) * 2;
                __half2 b2 = *reinterpret_cast<const __half2*>(g_bias + nBase + colw);
                __half2 v0 = __hadd2(__halves2half2(__float2half(acc[mi][ni][0]),
                                                    __float2half(acc[mi][ni][1])), b2);
                __half2 v1 = __hadd2(__halves2half2(__float2half(acc[mi][ni][2]),
                                                    __float2half(acc[mi][ni][3])), b2);
                *reinterpret_cast<float2*>(smf + row * EPI_F32_PITCH + colw) =
                    make_float2(__low2float(v0), __high2float(v0));
                *reinterpret_cast<float2*>(smf + (row + 8) * EPI_F32_PITCH + colw) =
                    make_float2(__low2float(v1), __high2float(v1));
            }
        }
        __syncthreads();
        float* out = (float*)outv;
#pragma unroll
        for (int i = 0; i < 16; i++) {
            int idx = tid + (i << 8);
            int r = idx >> 5;             // 32 float4 per 128-col row
            int c = (idx & 31) * 4;
            float4 v = *reinterpret_cast<float4*>(smf + r * EPI_F32_PITCH + c);
            *reinterpret_cast<float4*>(out + (size_t)(mBase + r) * EMB + nBase + c) = v;
        }
    } else {
        uint32_t* smu = reinterpret_cast<uint32_t*>(sm);
#pragma unroll
        for (int mi = 0; mi < 4; mi++) {
#pragma unroll
            for (int ni = 0; ni < 4; ni++) {
                int row  = wm + mi * 16 + (lane >> 2);
                int colw = wn + ni * 8 + (lane & 3) * 2;    // even
                __half2 b2 = *reinterpret_cast<const __half2*>(g_bias + nBase + colw);
                __half2 v0 = __hadd2(__halves2half2(__float2half(acc[mi][ni][0]),
                                                    __float2half(acc[mi][ni][1])), b2);
                __half2 v1 = __hadd2(__halves2half2(__float2half(acc[mi][ni][2]),
                                                    __float2half(acc[mi][ni][3])), b2);
                smu[row * EPI_F16_PITCH + (colw >> 1)] = h2_bits(v0);
                smu[(row + 8) * EPI_F16_PITCH + (colw >> 1)] = h2_bits(v1);
            }
        }
        __syncthreads();
        __half* out = (__half*)outv;
#pragma unroll
        for (int i = 0; i < 8; i++) {
            int idx = tid + (i << 8);
            int r = idx >> 4;             // 16 uint4 per 64-word row
            int q = idx & 15;
            uint4 v = *reinterpret_cast<uint4*>(smu + r * EPI_F16_PITCH + q * 4);
            *reinterpret_cast<uint4*>(out + (size_t)(mBase + r) * EMB + nBase + q * 8) = v;
        }
    }
}

// ---------------------------------------------------------------------------
extern "C" void kernel_launch(void* const* d_in, const int* in_sizes, int n_in,
                              void* d_out, int out_size) {
    const void* bigA = nullptr;
    const void* bigB = nullptr;
    const void* w    = nullptr;
    const void* bias = nullptr;
    for (int i = 0; i < n_in; i++) {
        if (in_sizes[i] == EMB)            bias = d_in[i];
        else if (in_sizes[i] == EMB * FFN) w    = d_in[i];
        else if (!bigA)                    bigA = d_in[i];
        else                               bigB = d_in[i];
    }

    prep_k<<<PREP_BLOCKS, 256>>>(bigA, bigB, w, bias);

    static int smem_set = 0;
    if (!smem_set) {
        cudaFuncSetAttribute(gemm_k, cudaFuncAttributeMaxDynamicSharedMemorySize, SMEM_TOTAL);
        smem_set = 1;
    }
    dim3 grid(EMB / BN, N_ROWS / BM);   // 8 x 64 = 512 CTAs, n-tiles fast
    gemm_k<<<grid, 256, SMEM_TOTAL>>>(d_out, bigA, bigB);
}